// round 8
// baseline (speedup 1.0000x reference)
#include <cuda_runtime.h>
#include <math.h>

// LSEP loss: out = log1p( sum_rows (sum_{t==0} e^x) * (sum_{t>0} e^{-x}) )
// input: [32768, 1000] fp32, target: [32768, 1000] int32 (values in {0,1}),
// out: [1] fp32.
//
// Single-kernel design: warp-per-row, float4/int4 loads, arithmetic routing
// (no predication): since t in {0,1},
//   c  = fma(tf, -2*log2e, log2e)        // +log2e if t==0, -log2e if t==1
//   e  = exp2(x * c)                     // = exp(x) or exp(-x)
//   S    += e                            // sum of ALL exps
//   spos  = fma(tf, e, spos)             // sum over t==1 of exp(-x)
//   sneg  = S - spos  (after warp reduce)
// One double RED per block (4096 total). Last block (ticket counter) does
// log1p and resets globals: 0 -> sum -> 0 per launch, graph-replay safe.

#define ROWS 32768
#define COLS 1000
#define VEC4_PER_ROW (COLS / 4)   // 250
#define WARPS_PER_BLOCK 8
#define THREADS (WARPS_PER_BLOCK * 32)
#define GRID (ROWS / WARPS_PER_BLOCK)

#define LOG2E 1.4426950408889634f

__device__ double g_total;          // static-init 0; reset to 0 by last block
__device__ unsigned int g_done;     // static-init 0; reset to 0 by last block

__global__ __launch_bounds__(THREADS) void lsep_kernel(
    const float* __restrict__ input,
    const int* __restrict__ target,
    float* __restrict__ out)
{
    const int warp = threadIdx.x >> 5;
    const int lane = threadIdx.x & 31;
    const int row  = blockIdx.x * WARPS_PER_BLOCK + warp;

    const float4* in4 = reinterpret_cast<const float4*>(input) + (size_t)row * VEC4_PER_ROW;
    const int4*   tg4 = reinterpret_cast<const int4*>(target)  + (size_t)row * VEC4_PER_ROW;

    float S    = 0.0f;   // sum of all exps (both classes)
    float spos = 0.0f;   // sum_{t==1} exp(-x)

    #pragma unroll 4
    for (int j = lane; j < VEC4_PER_ROW; j += 32) {
        float4 x = __ldg(&in4[j]);
        int4   t = __ldg(&tg4[j]);

        {
            float tf = (float)t.x;
            float c  = fmaf(tf, -2.0f * LOG2E, LOG2E);
            float e  = exp2f(x.x * c);
            S += e;
            spos = fmaf(tf, e, spos);
        }
        {
            float tf = (float)t.y;
            float c  = fmaf(tf, -2.0f * LOG2E, LOG2E);
            float e  = exp2f(x.y * c);
            S += e;
            spos = fmaf(tf, e, spos);
        }
        {
            float tf = (float)t.z;
            float c  = fmaf(tf, -2.0f * LOG2E, LOG2E);
            float e  = exp2f(x.z * c);
            S += e;
            spos = fmaf(tf, e, spos);
        }
        {
            float tf = (float)t.w;
            float c  = fmaf(tf, -2.0f * LOG2E, LOG2E);
            float e  = exp2f(x.w * c);
            S += e;
            spos = fmaf(tf, e, spos);
        }
    }

    // warp reduction of both partials
    #pragma unroll
    for (int off = 16; off > 0; off >>= 1) {
        S    += __shfl_xor_sync(0xFFFFFFFFu, S, off);
        spos += __shfl_xor_sync(0xFFFFFFFFu, spos, off);
    }

    __shared__ double s_prod[WARPS_PER_BLOCK];
    if (lane == 0) {
        float sneg = S - spos;   // sum_{t==0} exp(x)
        s_prod[warp] = (double)sneg * (double)spos;
    }
    __syncthreads();

    if (warp == 0) {
        double v = (lane < WARPS_PER_BLOCK) ? s_prod[lane] : 0.0;
        #pragma unroll
        for (int off = 4; off > 0; off >>= 1) {
            v += __shfl_xor_sync(0xFFFFFFFFu, v, off);
        }
        if (lane == 0) {
            atomicAdd(&g_total, v);          // no return use -> RED.F64 (L2-side)
            __threadfence();
            unsigned int ticket = atomicAdd(&g_done, 1u);
            if (ticket == (unsigned int)(GRID - 1)) {
                // Read through the L2 atomic path (not a plain cached LDG) so the
                // value observed is the authoritative atomic accumulator.
                double total = atomicAdd(&g_total, 0.0);
                out[0] = (float)log1p(total);
                g_total = 0.0;               // reset for next graph replay
                g_done  = 0u;
            }
        }
    }
}

extern "C" void kernel_launch(void* const* d_in, const int* in_sizes, int n_in,
                              void* d_out, int out_size) {
    const float* input  = (const float*)d_in[0];
    const int*   target = (const int*)d_in[1];
    float*       out    = (float*)d_out;

    lsep_kernel<<<GRID, THREADS>>>(input, target, out);
}

// round 9
// speedup vs baseline: 1.2268x; 1.2268x over previous
#include <cuda_runtime.h>
#include <math.h>

// LSEP loss: out = log1p( sum_rows (sum_{t==0} e^x) * (sum_{t>0} e^{-x}) )
// input: [32768, 1000] fp32, target: [32768, 1000] int32 (values in {0,1}),
// out: [1] fp32.
//
// R9: lean 6-instr/element math path (ISETP+FSEL+FMUL+MUFU+2xFADD) using
// inline ex2.approx (flag-independent), front-batched 4xLDG.128 per step,
// 64-reg budget via __launch_bounds__(256,4). Warp-per-row; per-row
// S = sum(all exps), P = sum_{t==1} exp(-x); sneg = S - P after reduce.
// One double RED per block; last block (ticket) does log1p + resets globals
// (0 -> sum -> 0 per launch, graph-replay safe).

#define ROWS 32768
#define COLS 1000
#define VEC4_PER_ROW (COLS / 4)   // 250
#define WARPS_PER_BLOCK 8
#define THREADS (WARPS_PER_BLOCK * 32)
#define GRID (ROWS / WARPS_PER_BLOCK)

#define LOG2E 1.4426950408889634f

__device__ double g_total;          // static-init 0; reset to 0 by last block
__device__ unsigned int g_done;     // static-init 0; reset to 0 by last block

// 6 instrs/element: ISETP (shared by SEL + pred), FSEL, FMUL, MUFU.EX2,
// FADD (S), predicated FADD (P). exp(±x) == ex2(x * ±log2e).
__device__ __forceinline__ void proc4(float4 x, int4 t, float& S, float& P)
{
    float c0 = (t.x != 0) ? -LOG2E : LOG2E;
    float c1 = (t.y != 0) ? -LOG2E : LOG2E;
    float c2 = (t.z != 0) ? -LOG2E : LOG2E;
    float c3 = (t.w != 0) ? -LOG2E : LOG2E;

    float e0, e1, e2, e3;
    asm("ex2.approx.ftz.f32 %0, %1;" : "=f"(e0) : "f"(x.x * c0));
    asm("ex2.approx.ftz.f32 %0, %1;" : "=f"(e1) : "f"(x.y * c1));
    asm("ex2.approx.ftz.f32 %0, %1;" : "=f"(e2) : "f"(x.z * c2));
    asm("ex2.approx.ftz.f32 %0, %1;" : "=f"(e3) : "f"(x.w * c3));

    S += (e0 + e1) + (e2 + e3);
    if (t.x != 0) P += e0;
    if (t.y != 0) P += e1;
    if (t.z != 0) P += e2;
    if (t.w != 0) P += e3;
}

__global__ __launch_bounds__(THREADS, 4) void lsep_kernel(
    const float* __restrict__ input,
    const int* __restrict__ target,
    float* __restrict__ out)
{
    const int warp = threadIdx.x >> 5;
    const int lane = threadIdx.x & 31;
    const int row  = blockIdx.x * WARPS_PER_BLOCK + warp;

    const float4* in4 = reinterpret_cast<const float4*>(input) + (size_t)row * VEC4_PER_ROW;
    const int4*   tg4 = reinterpret_cast<const int4*>(target)  + (size_t)row * VEC4_PER_ROW;

    float S = 0.0f;   // sum of all exps (both classes)
    float P = 0.0f;   // sum_{t==1} exp(-x)

    // 250 vec4s per row, lanes stride 32: indices lane + k*32, k = 0..7.
    // k = 0..6 are valid for all lanes (lane+192 <= 223 < 250); k = 7 only
    // for lane < 26. Process in pairs: 4 LDG.128 front-batched per step.
    #pragma unroll
    for (int k = 0; k < 3; k++) {
        int j0 = lane + k * 64;
        int j1 = j0 + 32;
        float4 x0 = __ldg(&in4[j0]);
        int4   t0 = __ldg(&tg4[j0]);
        float4 x1 = __ldg(&in4[j1]);
        int4   t1 = __ldg(&tg4[j1]);
        proc4(x0, t0, S, P);
        proc4(x1, t1, S, P);
    }
    {
        int j0 = lane + 192;           // always valid
        int j1 = j0 + 32;              // valid iff lane < 26
        float4 x0 = __ldg(&in4[j0]);
        int4   t0 = __ldg(&tg4[j0]);
        if (j1 < VEC4_PER_ROW) {
            float4 x1 = __ldg(&in4[j1]);
            int4   t1 = __ldg(&tg4[j1]);
            proc4(x0, t0, S, P);
            proc4(x1, t1, S, P);
        } else {
            proc4(x0, t0, S, P);
        }
    }

    // warp reduction of both partials
    #pragma unroll
    for (int off = 16; off > 0; off >>= 1) {
        S += __shfl_xor_sync(0xFFFFFFFFu, S, off);
        P += __shfl_xor_sync(0xFFFFFFFFu, P, off);
    }

    __shared__ double s_prod[WARPS_PER_BLOCK];
    if (lane == 0) {
        float sneg = S - P;   // sum_{t==0} exp(x)
        s_prod[warp] = (double)sneg * (double)P;
    }
    __syncthreads();

    if (warp == 0) {
        double v = (lane < WARPS_PER_BLOCK) ? s_prod[lane] : 0.0;
        #pragma unroll
        for (int off = 4; off > 0; off >>= 1) {
            v += __shfl_xor_sync(0xFFFFFFFFu, v, off);
        }
        if (lane == 0) {
            atomicAdd(&g_total, v);          // no return use -> RED.F64 (L2-side)
            __threadfence();
            unsigned int ticket = atomicAdd(&g_done, 1u);
            if (ticket == (unsigned int)(GRID - 1)) {
                // Read through the L2 atomic path so we observe the
                // authoritative atomic accumulator, not a stale cached line.
                double total = atomicAdd(&g_total, 0.0);
                out[0] = (float)log1p(total);
                g_total = 0.0;               // reset for next graph replay
                g_done  = 0u;
            }
        }
    }
}

extern "C" void kernel_launch(void* const* d_in, const int* in_sizes, int n_in,
                              void* d_out, int out_size) {
    const float* input  = (const float*)d_in[0];
    const int*   target = (const int*)d_in[1];
    float*       out    = (float*)d_out;

    lsep_kernel<<<GRID, THREADS>>>(input, target, out);
}

// round 11
// speedup vs baseline: 1.2725x; 1.0372x over previous
#include <cuda_runtime.h>
#include <math.h>

// LSEP loss: out = log1p( sum_rows (sum_{t==0} e^x) * (sum_{t>0} e^{-x}) )
// input: [32768, 1000] fp32, target: [32768, 1000] int32 (values in {0,1}),
// out: [1] fp32.
//
// R10: persistent single-wave grid (592 = 148 SMs x 4 resident CTAs), each
// block strides over row-groups; warp-per-row inside a group. Lean 6-instr
// math (ISETP+FSEL+FMUL+MUFU.EX2+2xFADD via inline ex2.approx), 4x LDG.128
// front-batched per step, __ldcs streaming hints. Per-warp double product
// accumulator across rows -> one block reduce + one RED.F64 per block (592
// total). Last block (ticket) does log1p + resets globals (0 -> sum -> 0
// per launch, graph-replay safe).

#define ROWS 32768
#define COLS 1000
#define VEC4_PER_ROW (COLS / 4)   // 250
#define WARPS_PER_BLOCK 8
#define THREADS (WARPS_PER_BLOCK * 32)
#define ROW_GROUPS (ROWS / WARPS_PER_BLOCK)   // 4096
#define GRID_P 592                            // 148 SMs x 4 CTAs -> one wave

#define LOG2E 1.4426950408889634f

__device__ double g_total;          // static-init 0; reset to 0 by last block
__device__ unsigned int g_done;     // static-init 0; reset to 0 by last block

// 6 instrs/element: ISETP (shared by SEL + pred), FSEL, FMUL, MUFU.EX2,
// FADD (S), predicated FADD (P). exp(+-x) == ex2(x * +-log2e).
__device__ __forceinline__ void proc4(float4 x, int4 t, float& S, float& P)
{
    float c0 = (t.x != 0) ? -LOG2E : LOG2E;
    float c1 = (t.y != 0) ? -LOG2E : LOG2E;
    float c2 = (t.z != 0) ? -LOG2E : LOG2E;
    float c3 = (t.w != 0) ? -LOG2E : LOG2E;

    float e0, e1, e2, e3;
    asm("ex2.approx.ftz.f32 %0, %1;" : "=f"(e0) : "f"(x.x * c0));
    asm("ex2.approx.ftz.f32 %0, %1;" : "=f"(e1) : "f"(x.y * c1));
    asm("ex2.approx.ftz.f32 %0, %1;" : "=f"(e2) : "f"(x.z * c2));
    asm("ex2.approx.ftz.f32 %0, %1;" : "=f"(e3) : "f"(x.w * c3));

    S += (e0 + e1) + (e2 + e3);
    if (t.x != 0) P += e0;
    if (t.y != 0) P += e1;
    if (t.z != 0) P += e2;
    if (t.w != 0) P += e3;
}

__global__ __launch_bounds__(THREADS, 4) void lsep_kernel(
    const float* __restrict__ input,
    const int* __restrict__ target,
    float* __restrict__ out)
{
    const int warp = threadIdx.x >> 5;
    const int lane = threadIdx.x & 31;

    double acc = 0.0;   // per-warp sum over processed rows of sneg*spos (lane0 meaningful)

    for (int iter = blockIdx.x; iter < ROW_GROUPS; iter += GRID_P) {
        const int row = iter * WARPS_PER_BLOCK + warp;

        const float4* in4 = reinterpret_cast<const float4*>(input) + (size_t)row * VEC4_PER_ROW;
        const int4*   tg4 = reinterpret_cast<const int4*>(target)  + (size_t)row * VEC4_PER_ROW;

        float S = 0.0f;   // sum of all exps (both classes)
        float P = 0.0f;   // sum_{t==1} exp(-x)

        // 250 vec4s per row, lanes stride 32: j = lane + k*32, k = 0..7.
        // k = 0..6 valid for all lanes; k = 7 only for lane < 26.
        // Pairs of chunks: 4 LDG.128 front-batched per step (2 KB/warp in flight).
        #pragma unroll
        for (int k = 0; k < 3; k++) {
            int j0 = lane + k * 64;
            int j1 = j0 + 32;
            float4 x0 = __ldcs(&in4[j0]);
            int4   t0 = __ldcs(&tg4[j0]);
            float4 x1 = __ldcs(&in4[j1]);
            int4   t1 = __ldcs(&tg4[j1]);
            proc4(x0, t0, S, P);
            proc4(x1, t1, S, P);
        }
        {
            int j0 = lane + 192;           // always valid
            int j1 = j0 + 32;              // valid iff lane < 26
            float4 x0 = __ldcs(&in4[j0]);
            int4   t0 = __ldcs(&tg4[j0]);
            if (j1 < VEC4_PER_ROW) {
                float4 x1 = __ldcs(&in4[j1]);
                int4   t1 = __ldcs(&tg4[j1]);
                proc4(x0, t0, S, P);
                proc4(x1, t1, S, P);
            } else {
                proc4(x0, t0, S, P);
            }
        }

        // warp reduction of both partials
        #pragma unroll
        for (int off = 16; off > 0; off >>= 1) {
            S += __shfl_xor_sync(0xFFFFFFFFu, S, off);
            P += __shfl_xor_sync(0xFFFFFFFFu, P, off);
        }

        if (lane == 0) {
            float sneg = S - P;   // sum_{t==0} exp(x)
            acc += (double)sneg * (double)P;
        }
    }

    // block reduction of per-warp accumulators (once per kernel)
    __shared__ double s_prod[WARPS_PER_BLOCK];
    if (lane == 0) s_prod[warp] = acc;
    __syncthreads();

    if (warp == 0) {
        double v = (lane < WARPS_PER_BLOCK) ? s_prod[lane] : 0.0;
        #pragma unroll
        for (int off = 4; off > 0; off >>= 1) {
            v += __shfl_xor_sync(0xFFFFFFFFu, v, off);
        }
        if (lane == 0) {
            atomicAdd(&g_total, v);          // no return use -> RED.F64 (L2-side)
            __threadfence();
            unsigned int ticket = atomicAdd(&g_done, 1u);
            if (ticket == (unsigned int)(GRID_P - 1)) {
                // Read through the L2 atomic path so we observe the
                // authoritative atomic accumulator, not a stale cached line.
                double total = atomicAdd(&g_total, 0.0);
                out[0] = (float)log1p(total);
                g_total = 0.0;               // reset for next graph replay
                g_done  = 0u;
            }
        }
    }
}

extern "C" void kernel_launch(void* const* d_in, const int* in_sizes, int n_in,
                              void* d_out, int out_size) {
    const float* input  = (const float*)d_in[0];
    const int*   target = (const int*)d_in[1];
    float*       out    = (float*)d_out;

    lsep_kernel<<<GRID_P, THREADS>>>(input, target, out);
}

// round 12
// speedup vs baseline: 1.2851x; 1.0099x over previous
#include <cuda_runtime.h>
#include <math.h>

// LSEP loss: out = log1p( sum_rows (sum_{t==0} e^x) * (sum_{t>0} e^{-x}) )
// input: [32768, 1000] fp32, target: [32768, 1000] int32 (values in {0,1}),
// out: [1] fp32.
//
// R12: R11 (persistent single-wave 592-CTA grid, lean ex2.approx math,
// __ldcs streaming, one RED.F64/block, ticket finalize) + software-pipelined
// pair-steps: the next pair's 4x LDG.128 are issued BEFORE the current pair
// is processed, so load latency overlaps MUFU/FADD chains instead of being
// exposed at each step boundary. Two pairs live = 32 data regs, fits the
// 64-reg / 4-CTA budget. Tail chunk (k=7, lanes >= 26 invalid) handled by
// clamping its load index to a safe in-row address and skipping its
// contribution with a lane guard.

#define ROWS 32768
#define COLS 1000
#define VEC4_PER_ROW (COLS / 4)   // 250
#define WARPS_PER_BLOCK 8
#define THREADS (WARPS_PER_BLOCK * 32)
#define ROW_GROUPS (ROWS / WARPS_PER_BLOCK)   // 4096
#define GRID_P 592                            // 148 SMs x 4 CTAs -> one wave

#define LOG2E 1.4426950408889634f

__device__ double g_total;          // static-init 0; reset to 0 by last block
__device__ unsigned int g_done;     // static-init 0; reset to 0 by last block

// 6 instrs/element: ISETP (shared by SEL + pred), FSEL, FMUL, MUFU.EX2,
// FADD (S), predicated FADD (P). exp(+-x) == ex2(x * +-log2e).
__device__ __forceinline__ void proc4(float4 x, int4 t, float& S, float& P)
{
    float c0 = (t.x != 0) ? -LOG2E : LOG2E;
    float c1 = (t.y != 0) ? -LOG2E : LOG2E;
    float c2 = (t.z != 0) ? -LOG2E : LOG2E;
    float c3 = (t.w != 0) ? -LOG2E : LOG2E;

    float e0, e1, e2, e3;
    asm("ex2.approx.ftz.f32 %0, %1;" : "=f"(e0) : "f"(x.x * c0));
    asm("ex2.approx.ftz.f32 %0, %1;" : "=f"(e1) : "f"(x.y * c1));
    asm("ex2.approx.ftz.f32 %0, %1;" : "=f"(e2) : "f"(x.z * c2));
    asm("ex2.approx.ftz.f32 %0, %1;" : "=f"(e3) : "f"(x.w * c3));

    S += (e0 + e1) + (e2 + e3);
    if (t.x != 0) P += e0;
    if (t.y != 0) P += e1;
    if (t.z != 0) P += e2;
    if (t.w != 0) P += e3;
}

__global__ __launch_bounds__(THREADS, 4) void lsep_kernel(
    const float* __restrict__ input,
    const int* __restrict__ target,
    float* __restrict__ out)
{
    const int warp = threadIdx.x >> 5;
    const int lane = threadIdx.x & 31;
    const bool tail_ok = (lane < 26);   // k=7 chunk valid only for lanes 0..25

    double acc = 0.0;   // per-warp sum over processed rows of sneg*spos (lane0 meaningful)

    for (int iter = blockIdx.x; iter < ROW_GROUPS; iter += GRID_P) {
        const int row = iter * WARPS_PER_BLOCK + warp;

        const float4* in4 = reinterpret_cast<const float4*>(input) + (size_t)row * VEC4_PER_ROW;
        const int4*   tg4 = reinterpret_cast<const int4*>(target)  + (size_t)row * VEC4_PER_ROW;

        float S = 0.0f;   // sum of all exps (both classes)
        float P = 0.0f;   // sum_{t==1} exp(-x)

        // 250 vec4s/row, j = lane + k*32, k = 0..7 (k=7 only lane<26).
        // 4 pair-steps of 2 chunks each; 2-stage pipeline: issue next pair's
        // 4 LDG.128 before consuming the current pair.
        float4 xa0 = __ldcs(&in4[lane]);
        int4   ta0 = __ldcs(&tg4[lane]);
        float4 xa1 = __ldcs(&in4[lane + 32]);
        int4   ta1 = __ldcs(&tg4[lane + 32]);

        #pragma unroll
        for (int s = 0; s < 3; s++) {
            int b0 = lane + (s + 1) * 64;
            int b1 = b0 + 32;
            if (s == 2 && !tail_ok) b1 = b0;   // clamp: safe dup read, skipped later

            float4 xb0 = __ldcs(&in4[b0]);
            int4   tb0 = __ldcs(&tg4[b0]);
            float4 xb1 = __ldcs(&in4[b1]);
            int4   tb1 = __ldcs(&tg4[b1]);

            proc4(xa0, ta0, S, P);
            proc4(xa1, ta1, S, P);

            xa0 = xb0; ta0 = tb0; xa1 = xb1; ta1 = tb1;
        }
        proc4(xa0, ta0, S, P);
        if (tail_ok) proc4(xa1, ta1, S, P);

        // warp reduction of both partials
        #pragma unroll
        for (int off = 16; off > 0; off >>= 1) {
            S += __shfl_xor_sync(0xFFFFFFFFu, S, off);
            P += __shfl_xor_sync(0xFFFFFFFFu, P, off);
        }

        if (lane == 0) {
            float sneg = S - P;   // sum_{t==0} exp(x)
            acc += (double)sneg * (double)P;
        }
    }

    // block reduction of per-warp accumulators (once per kernel)
    __shared__ double s_prod[WARPS_PER_BLOCK];
    if (lane == 0) s_prod[warp] = acc;
    __syncthreads();

    if (warp == 0) {
        double v = (lane < WARPS_PER_BLOCK) ? s_prod[lane] : 0.0;
        #pragma unroll
        for (int off = 4; off > 0; off >>= 1) {
            v += __shfl_xor_sync(0xFFFFFFFFu, v, off);
        }
        if (lane == 0) {
            atomicAdd(&g_total, v);          // no return use -> RED.F64 (L2-side)
            __threadfence();
            unsigned int ticket = atomicAdd(&g_done, 1u);
            if (ticket == (unsigned int)(GRID_P - 1)) {
                // Read through the L2 atomic path so we observe the
                // authoritative atomic accumulator, not a stale cached line.
                double total = atomicAdd(&g_total, 0.0);
                out[0] = (float)log1p(total);
                g_total = 0.0;               // reset for next graph replay
                g_done  = 0u;
            }
        }
    }
}

extern "C" void kernel_launch(void* const* d_in, const int* in_sizes, int n_in,
                              void* d_out, int out_size) {
    const float* input  = (const float*)d_in[0];
    const int*   target = (const int*)d_in[1];
    float*       out    = (float*)d_out;

    lsep_kernel<<<GRID_P, THREADS>>>(input, target, out);
}